// round 16
// baseline (speedup 1.0000x reference)
#include <cuda_runtime.h>

// CTC forward scan, linear domain, x4-factored:
//   G_j(t+1) = W_t[s_j]*G_{j-1}(t) + G_j(t),  W_t[s] = exp(x[t,s]-x[t,4])
//   fwd[j] = log(G) + e*ln2 + sum_t x4
//
// R15: TWO warps per batch with CHUNK-GRANULARITY coupling (1 barrier / 32
// steps — R9 failed at 8-step granularity, this amortizes it 4x further):
//   warp0 tile = positions 0..287  : touches j=0 boundary -> ALWAYS exact,
//                                    needs no incoming data, ever.
//   warp1 tile = positions 224..511: erodes 1 pos/step from its left edge;
//                                    32-wide overlap == chunk length, so a
//                                    once-per-chunk refresh of positions
//                                    224..255 from warp0 keeps owned >=256
//                                    exact.
// Both warps: PB=9 (9 positions/lane), KB=8 trapezoid, NU=16 updates/step,
// NP=8 pair rows -> ladder = 8 LDS.64 + 16 FFMA per step (vs 12+23 for the
// old single-warp PB=16). Intra-warp halo stays shfl (proven R7/R12 code).
// W pair-table shared per CTA (conflict-free float2, stride 33), convert
// split 16 taus per warp. Refresh/publish carry per-position (g, e, E)
// with the proven common-scale rule (all rescale factors <= 1: no overflow;
// flush-to-zero only when ratio > ~2^127 => correct).
// grid = nb CTAs x 64 threads, 2 CTAs/SM -> 512 busy SMSPs (was 256).

#define XCH    32
#define KB     8
#define PB     9
#define NSTATE (KB + PB)    // 17
#define NU     16           // PB + KB - 1 (even -> NP exact pairs)
#define NP     8
#define PSTR   33
#define TPB    64
#define NEGE   (-(1 << 29))

__device__ __forceinline__ float exp2i_le(int d) {
    int b = d + 127;
    b = b < 0 ? 0 : (b > 254 ? 254 : b);
    return __int_as_float(b << 23);
}

__global__ __launch_bounds__(TPB, 2)
void ctc_fwd(const float* __restrict__ x,
             const int*   __restrict__ seqs,
             const int*   __restrict__ seqlens,
             float*       __restrict__ out,
             int nt, int nb, int ns)
{
    __shared__ float2 shP[2][16 * PSTR];   // W pair table, double buffered
    __shared__ float  gb[2][32];           // boundary G, positions 224..255
    __shared__ int2   eb[2][32];           // (e, E=e+ilogb(mx)) per position
    __shared__ float  gall[512];
    __shared__ int    earr[512];
    __shared__ double dsum[2];

    const int tid   = threadIdx.x;
    const int w     = tid >> 5;            // warp in CTA (0 left, 1 right)
    const int l     = tid & 31;
    const int bb    = blockIdx.x;
    const int sl    = seqlens[bb];
    const int tile0 = w ? 224 : 0;
    const int jmin  = tile0 + l * PB;      // lane's first position

    if (tid < 32) {
        gb[0][tid] = 0.f; gb[1][tid] = 0.f;
        eb[0][tid] = make_int2(0, NEGE);
        eb[1][tid] = make_int2(0, NEGE);
    }

    // move indices: update k writes G[k+1] (position jmin+k+1-KB), uses
    // seqs[jmin+k-KB]; NU=16 even -> 8 exact pair rows
    int s[NU];
    #pragma unroll
    for (int k = 0; k < NU; ++k) {
        int q = jmin + k - KB;
        s[k] = (q >= 0 && q < ns) ? seqs[(long long)bb * ns + q] : 0;
    }
    int pq[NP];
    #pragma unroll
    for (int q = 0; q < NP; ++q)
        pq[q] = (s[2 * q] * 4 + s[2 * q + 1]) * PSTR;

    float G[NSTATE];
    #pragma unroll
    for (int i = 0; i < NSTATE; ++i) G[i] = 0.f;
    if (w == 0 && l == 0) G[KB] = 1.0f;    // position 0: fwd=0 -> G=1
    int e = 0;

    // W loader: lanes 0..15 of each warp; warp w covers taus 16w..16w+15
    const bool ldr = (l < 16);
    const int  tau = w * 16 + l;
    float a0 = 0.f, a1 = 0.f, a2 = 0.f, a3 = 0.f, a4 = 0.f;
    double x4s = 0.0;

    auto prefetch = [&](int c) {           // LDG only into registers
        if (ldr) {
            int tt = c * XCH + tau;
            if (tt < nt) {
                const float* xp = x + ((long long)tt * nb + bb) * 5;
                a0 = xp[0]; a1 = xp[1]; a2 = xp[2]; a3 = xp[3]; a4 = xp[4];
            } else {
                a0 = a1 = a2 = a3 = -1e9f; // exp->0: steps past nt freeze G
                a4 = 0.f;
            }
        }
    };
    auto convert = [&](int c) {            // expf + 16 STS.64 pair rows
        if (ldr) {
            float wv[4];
            wv[0] = __expf(a0 - a4); wv[1] = __expf(a1 - a4);
            wv[2] = __expf(a2 - a4); wv[3] = __expf(a3 - a4);
            float2* row = &shP[c & 1][tau];
            #pragma unroll
            for (int aa = 0; aa < 4; ++aa)
                #pragma unroll
                for (int bq = 0; bq < 4; ++bq)
                    row[(aa * 4 + bq) * PSTR] = make_float2(wv[aa], wv[bq]);
            if (c * XCH + tau < nt) x4s += (double)a4;
        }
    };

    prefetch(0); convert(0); prefetch(1);
    __syncthreads();                        // table buf0 + gb init visible

    const int NC = (nt + XCH - 1) / XCH;
    for (int c = 0; c < NC; ++c) {
        // ---- refresh: warp1 lanes whose tile slots dip below 256 ----
        if (w == 1 && jmin < 256) {
            float mx0 = G[KB];
            #pragma unroll
            for (int i = 1; i < PB; ++i) mx0 = fmaxf(mx0, G[KB + i]);
            int cc = (mx0 > 0.f)
                   ? (e + ((__float_as_int(mx0) >> 23) - 127)) : NEGE;
            #pragma unroll
            for (int i = 0; i < PB; ++i) {
                int p = jmin + i;
                if (p < 256) {
                    float g = gb[c & 1][p - 224];
                    int   E = eb[c & 1][p - 224].y;
                    if (g > 0.f && E > cc) cc = E;
                }
            }
            if (cc == NEGE) cc = 0;
            float rsn = exp2i_le(e - cc);
            #pragma unroll
            for (int i = 0; i < PB; ++i) {
                int p = jmin + i;
                if (p < 256) {              // import exact value from warp0
                    float g  = gb[c & 1][p - 224];
                    int   es = eb[c & 1][p - 224].x;
                    G[KB + i] = g * exp2i_le(es - cc);
                } else {
                    G[KB + i] *= rsn;       // keep own, rescale to cc
                }
            }
            e = cc;
        }

        const float2* rp[NP];
        {
            const float2* cbb = &shP[c & 1][0];
            #pragma unroll
            for (int q = 0; q < NP; ++q) rp[q] = cbb + pq[q];
        }
        #pragma unroll 1
        for (int r = 0; r < XCH / KB; ++r) {
            // ---- exchange (shfl halo, common-scale mixing) ----
            float mx = G[KB];
            #pragma unroll
            for (int i = KB + 1; i < NSTATE; ++i) mx = fmaxf(mx, G[i]);
            int ex = (__float_as_int(mx) >> 23) - 127;
            int hm = (mx > 0.f) ? 1 : 0;
            int pack  = (e << 9) | ((ex + 128) << 1) | hm;
            int packL = __shfl_up_sync(0xffffffffu, pack, 1);
            float h[KB];
            #pragma unroll
            for (int i = 0; i < KB; ++i)    // left lane's top KB positions
                h[i] = __shfl_up_sync(0xffffffffu, G[PB + i], 1);
            int hL  = (l == 0) ? 0 : (packL & 1);   // warp left edge: no in
            int exL = ((packL >> 1) & 255) - 128;
            int eL  = packL >> 9;
            int EO = hm ? (e + ex)   : NEGE;
            int EL = hL ? (eL + exL) : NEGE;
            int cc = EO > EL ? EO : EL;
            if (cc == NEGE) cc = 0;
            float rs = exp2i_le(e - cc);
            float rl = hL ? exp2i_le(eL - cc) : 0.f;
            bool act = (jmin <= sl) && (hm || hL);
            if (act) {
                #pragma unroll
                for (int i = 0; i < KB; ++i) G[i] = h[i] * rl;
                #pragma unroll
                for (int i = KB; i < NSTATE; ++i) G[i] *= rs;
                e = cc;
                // ---- ladder: KB steps, 8 LDS.64 + 16 FFMA each ----
                #pragma unroll
                for (int k = 0; k < KB; ++k) {
                    float2 W[NP];
                    #pragma unroll
                    for (int q = 0; q < NP; ++q) W[q] = rp[q][k];
                    #pragma unroll
                    for (int q = NP - 1; q >= 0; --q) {
                        G[2*q + 2] = fmaf(W[q].y, G[2*q + 1], G[2*q + 2]);
                        G[2*q + 1] = fmaf(W[q].x, G[2*q],     G[2*q + 1]);
                    }
                }
            }
            #pragma unroll
            for (int q = 0; q < NP; ++q) rp[q] += KB;
        }

        // ---- publish: warp0 lanes covering [224,256) -> parity buffer ----
        if (w == 0 && jmin + PB > 224 && jmin < 256) {
            float mx0 = G[KB];
            #pragma unroll
            for (int i = 1; i < PB; ++i) mx0 = fmaxf(mx0, G[KB + i]);
            int E = (mx0 > 0.f)
                  ? (e + ((__float_as_int(mx0) >> 23) - 127)) : NEGE;
            #pragma unroll
            for (int i = 0; i < PB; ++i) {
                int p = jmin + i;
                if (p >= 224 && p < 256) {
                    gb[(c + 1) & 1][p - 224] = G[KB + i];
                    eb[(c + 1) & 1][p - 224] = make_int2(e, E);
                }
            }
        }
        convert(c + 1);                     // regs from prefetch(c+1)
        prefetch(c + 2);
        __syncthreads();                    // publish + table visible
    }

    // ---- epilogue ----
    #pragma unroll
    for (int i = 0; i < PB; ++i) {
        int p = jmin + i;
        bool mine = (w == 0) ? (p < 256) : (p >= 256 && p < 512);
        if (mine) { gall[p] = G[KB + i]; earr[p] = e; }
    }
    {
        double v = x4s;
        #pragma unroll
        for (int o = 16; o; o >>= 1)
            v += __shfl_down_sync(0xffffffffu, v, o);
        if (l == 0) dsum[w] = v;
    }
    __syncthreads();
    if (tid == 0) {
        float  Gv = gall[sl];
        int    ev = earr[sl];
        double lv = (double)logf(Gv) + (double)ev * 0.6931471805599453
                  + dsum[0] + dsum[1];
        out[bb] = (float)(-lv / (double)nt);
    }
}

extern "C" void kernel_launch(void* const* d_in, const int* in_sizes, int n_in,
                              void* d_out, int out_size) {
    const float* x       = (const float*)d_in[0];
    const int*   seqs    = (const int*)  d_in[1];
    const int*   seqlens = (const int*)  d_in[2];
    float*       out     = (float*)d_out;

    const int nb = in_sizes[2];
    const int ns = in_sizes[1] / nb;
    const int nt = in_sizes[0] / (nb * 5);

    ctc_fwd<<<nb, TPB>>>(x, seqs, seqlens, out, nt, nb, ns);
}

// round 17
// speedup vs baseline: 1.0132x; 1.0132x over previous
#include <cuda_runtime.h>

// CTC forward scan, linear domain, x4-factored:
//   G_j(t+1) = W_t[s_j]*G_{j-1}(t) + G_j(t),  W_t[s] = exp(x[t,s]-x[t,4])
//   fwd[j] = log(G) + e*ln2 + sum_t x4
//
// R16 = R14 frame (best: 98.8us — single warp per batch, zero barriers,
// conflict-free float2 pair-table, launch_bounds(64,1)) with the ladder
// re-expressed in PACKED f32x2:
//   state packs P[j] = (G[j], G[j+D]), D = (KB+PB)/2. Pack-update i
//   (= updates u_i and u_{i+D} fused) is
//       P[i+1] += (W[s_i], W[s_{i+D}]) (x) P[i]     -- one fma.rn.f32x2
//   and the multiplier pack is a re-keyed row of the SAME 16-combo pair
//   table (row = s_i*4 + s_{i+D}). One leftover scalar update u_{D-1}
//   (reads G[D-1] saved to a temp before pack-update D-2; writes hi(P[0])
//   after pack-update 0). Ladder slots: 12 LDS.64 + 11 FFMA2 + 1 FFMA
//   (was 12 LDS.64 + 23 FFMA). Rescale uses mul.rn.f32x2.
// Numerically identical to R14 (FFMA2 = two independent FFMAs).

#define XCH  32
#define KB   8
#define PSTR 33
#define NBAT 2
#define TPB  (32 * NBAT)

typedef unsigned long long ull;

__device__ __forceinline__ float exp2i_le(int d) {
    int b = d + 127;
    b = b < 0 ? 0 : (b > 254 ? 254 : b);
    return __int_as_float(b << 23);
}

__device__ __forceinline__ ull mk2(float x, float y) {
    ull r; asm("mov.b64 %0, {%1, %2};" : "=l"(r) : "f"(x), "f"(y)); return r;
}
__device__ __forceinline__ void un2(ull v, float& x, float& y) {
    asm("mov.b64 {%0, %1}, %2;" : "=f"(x), "=f"(y) : "l"(v));
}
__device__ __forceinline__ void fma2(ull& d, ull a, ull b) {
    // d = a (x) b + d  (two independent fp32 FMAs in one issue slot)
    asm("fma.rn.f32x2 %0, %1, %2, %3;" : "=l"(d) : "l"(a), "l"(b), "l"(d));
}
__device__ __forceinline__ ull mul2(ull a, ull b) {
    ull r; asm("mul.rn.f32x2 %0, %1, %2;" : "=l"(r) : "l"(a), "l"(b)); return r;
}

template<int PB>
__device__ __forceinline__ void scan_batch(
    const float* __restrict__ x, const int* __restrict__ seqs,
    int sl, int bb, int nt, int nb, int ns,
    float* __restrict__ out,
    float2* __restrict__ shP,    // [2][16*PSTR]
    float*  __restrict__ gall,   // [32*PB]
    int*    __restrict__ eall)   // [32]
{
    constexpr int NS = KB + PB;           // state size (even)
    constexpr int D  = NS / 2;            // packs
    constexpr int NU = NS - 1;            // updates per step (odd)
    static_assert(NS % 2 == 0, "");
    const int l    = threadIdx.x & 31;
    const int jmin = l * PB;

    // move indices: update k writes G[k+1] (position jmin+k+1-KB), uses
    // seqs[jmin+k-KB]
    int s[NU];
    #pragma unroll
    for (int k = 0; k < NU; ++k) {
        int q = jmin + k - KB;
        s[k] = (q >= 0 && q < ns) ? seqs[(long long)bb * ns + q] : 0;
    }
    // pack rows: pack-update i multiplies by (W[s_i], W[s_{i+D}])
    int pq[D - 1];
    #pragma unroll
    for (int i = 0; i < D - 1; ++i)
        pq[i] = (s[i] * 4 + s[i + D]) * PSTR;
    const int pqL = (s[D - 1] * 4 + s[D - 1]) * PSTR;  // leftover (lo half)

    ull P[D];
    #pragma unroll
    for (int j = 0; j < D; ++j) P[j] = 0ull;
    if (l == 0) {                         // position 0: fwd=0 -> G[KB]=1
        if (KB < D) P[KB] = mk2(1.0f, 0.0f);
        else        P[KB - D] = mk2(0.0f, 1.0f);
    }
    int e = 0;

    float a0 = 0.f, a1 = 0.f, a2 = 0.f, a3 = 0.f, a4 = 0.f;
    double x4s = 0.0;

    auto prefetch = [&](int c) {          // LDG only (regs), one tau per lane
        int tt = c * XCH + l;
        if (tt < nt) {
            const float* xp = x + ((long long)tt * nb + bb) * 5;
            a0 = xp[0]; a1 = xp[1]; a2 = xp[2]; a3 = xp[3]; a4 = xp[4];
        } else {
            a0 = a1 = a2 = a3 = -1e9f;    // exp -> 0: steps past nt freeze G
            a4 = 0.f;
        }
    };
    auto convert = [&](int c) {           // expf + 16 STS.64 pair rows
        float w[4];
        w[0] = __expf(a0 - a4); w[1] = __expf(a1 - a4);
        w[2] = __expf(a2 - a4); w[3] = __expf(a3 - a4);
        float2* row = shP + (c & 1) * (16 * PSTR) + l;
        #pragma unroll
        for (int aa = 0; aa < 4; ++aa)
            #pragma unroll
            for (int bq = 0; bq < 4; ++bq)
                row[(aa * 4 + bq) * PSTR] = make_float2(w[aa], w[bq]);
        if (c * XCH + l < nt) x4s += (double)a4;
    };

    prefetch(0); convert(0); prefetch(1);
    __syncwarp();

    const int NC = (nt + XCH - 1) / XCH;
    for (int c = 0; c < NC; ++c) {
        const ull* rp[D - 1];
        const ull* rpL;
        {
            const ull* cbb = (const ull*)(shP + (c & 1) * (16 * PSTR));
            #pragma unroll
            for (int q = 0; q < D - 1; ++q) rp[q] = cbb + pq[q];
            rpL = cbb + pqL;
        }
        #pragma unroll 1
        for (int r = 0; r < XCH / KB; ++r) {
            // ---- exchange (shfl halo, common-scale mixing) ----
            float lox[D], hix[D];
            #pragma unroll
            for (int j = 0; j < D; ++j) un2(P[j], lox[j], hix[j]);

            // owned = G[KB..NS-1]: m<D -> lox[m], else hix[m-D]
            float mx = hix[D - 1];
            #pragma unroll
            for (int m = KB; m < D; ++m) mx = fmaxf(mx, lox[m]);
            #pragma unroll
            for (int m = 0; m < D - 1; ++m) mx = fmaxf(mx, hix[m]);

            int ex = (__float_as_int(mx) >> 23) - 127;
            int hm = (mx > 0.0f) ? 1 : 0;
            int pack  = (e << 9) | ((ex + 128) << 1) | hm;
            int packL = __shfl_up_sync(0xffffffffu, pack, 1);
            // top KB owned = G[PB..PB+KB-1] = hix[(PB-D) .. (PB-D)+KB-1]
            constexpr int HB = (PB - KB) / 2;   // = PB - D
            float h[KB];
            #pragma unroll
            for (int i = 0; i < KB; ++i)
                h[i] = __shfl_up_sync(0xffffffffu, hix[HB + i], 1);
            int hL  = (l == 0) ? 0 : (packL & 1);
            int exL = ((packL >> 1) & 255) - 128;
            int eL  = packL >> 9;              // arithmetic shift: sign kept
            const int NEG = -(1 << 29);
            int EO = hm ? (e + ex)   : NEG;
            int EL = hL ? (eL + exL) : NEG;
            int cc = EO > EL ? EO : EL;
            if (cc == NEG) cc = 0;
            float rs = exp2i_le(e - cc);       // <= 2^-ex -> post-mix <= 2
            float rl = hL ? exp2i_le(eL - cc) : 0.0f;
            {
                ull Flr = mk2(rl, rs);
                ull Fss = mk2(rs, rs);
                #pragma unroll
                for (int j = 0; j < KB; ++j)   // lo <- halo*rl, hi *= rs
                    P[j] = mul2(mk2(h[j], hix[j]), Flr);
                #pragma unroll
                for (int j = KB; j < D; ++j)   // both halves owned
                    P[j] = mul2(P[j], Fss);
            }
            e = cc;

            // ---- ladder: KB steps, 11 FFMA2 + 1 scalar FFMA each ----
            #pragma unroll
            for (int k = 0; k < KB; ++k) {
                ull Wp[D - 1];
                #pragma unroll
                for (int q = 0; q < D - 1; ++q) Wp[q] = rp[q][k];
                ull WLv = rpL[k];
                float tL, tH; un2(P[D - 1], tL, tH);   // save G[D-1]
                #pragma unroll
                for (int i = D - 2; i >= 0; --i)       // descending targets
                    fma2(P[i + 1], Wp[i], P[i]);
                float wl, wh; un2(WLv, wl, wh);
                float g0, gD; un2(P[0], g0, gD);       // leftover u_{D-1}
                P[0] = mk2(g0, fmaf(wl, tL, gD));      // G[D] += w*G[D-1]
            }
            #pragma unroll
            for (int q = 0; q < D - 1; ++q) rp[q] += KB;
            rpL += KB;
        }
        convert(c + 1);      // regs from prefetch(c+1)
        __syncwarp();        // cross-lane table visibility
        prefetch(c + 2);
    }

    // ---- epilogue ----
    {
        float lox[D], hix[D];
        #pragma unroll
        for (int j = 0; j < D; ++j) un2(P[j], lox[j], hix[j]);
        #pragma unroll
        for (int i = 0; i < PB; ++i) {
            int m = KB + i;
            gall[jmin + i] = (m < D) ? lox[m] : hix[m - D];
        }
    }
    eall[l] = e;
    double v = x4s;
    #pragma unroll
    for (int o = 16; o; o >>= 1)
        v += __shfl_down_sync(0xffffffffu, v, o);
    __syncwarp();
    if (l == 0) {
        float  Gv = gall[sl];
        int    ev = eall[sl / PB];
        double lv = (double)logf(Gv) + (double)ev * 0.6931471805599453 + v;
        out[bb] = (float)(-lv / (double)nt);
    }
}

__global__ __launch_bounds__(TPB, 1)
void ctc_fwd(const float* __restrict__ x,
             const int*   __restrict__ seqs,
             const int*   __restrict__ seqlens,
             float*       __restrict__ out,
             int nt, int nb, int ns)
{
    __shared__ float2 shP [NBAT][2 * 16 * PSTR];
    __shared__ float  gall[NBAT][512];
    __shared__ int    eall[NBAT][32];

    const int w  = threadIdx.x >> 5;
    const int bb = blockIdx.x * NBAT + w;
    if (bb >= nb) return;                  // warp-uniform exit
    const int sl = seqlens[bb];

    if (sl < 8 * 32)
        scan_batch<8>(x, seqs, sl, bb, nt, nb, ns, out,
                      shP[w], gall[w], eall[w]);
    else
        scan_batch<16>(x, seqs, sl, bb, nt, nb, ns, out,
                       shP[w], gall[w], eall[w]);
}

extern "C" void kernel_launch(void* const* d_in, const int* in_sizes, int n_in,
                              void* d_out, int out_size) {
    const float* x       = (const float*)d_in[0];
    const int*   seqs    = (const int*)  d_in[1];
    const int*   seqlens = (const int*)  d_in[2];
    float*       out     = (float*)d_out;

    const int nb = in_sizes[2];
    const int ns = in_sizes[1] / nb;
    const int nt = in_sizes[0] / (nb * 5);

    ctc_fwd<<<(nb + NBAT - 1) / NBAT, TPB>>>(x, seqs, seqlens, out, nt, nb, ns);
}